// round 4
// baseline (speedup 1.0000x reference)
#include <cuda_runtime.h>
#include <math.h>

// Problem constants
#define NN   50000
#define EE   800000
#define DD   128
#define HH   4
#define EDD  32
#define KDIM 129          // D+1 input dim
#define QKS  132          // per-(n,h) stride for q/k: [space 0..127, time at 128, pad]
#define EPSF 1e-8f
#define SCALE_INV 0.08838834764831845f   // 1/sqrt(128)
#define CHALF     5.656854249492381f     // sqrt(128)/2

#define NPAD 50176        // NN padded to 256 multiple (196 blocks)
#define NBLK 196

// ---------------- scratch (static device globals; no allocation) -------------
__device__ float g_q[NN * HH * QKS];      // 105.6 MB
__device__ float g_k[NN * HH * QKS];      // 105.6 MB
__device__ float g_tan[NN * HH * DD];     // 102.4 MB
__device__ float g_logits[EE * HH];       // 12.8 MB
__device__ int   g_cnt[NPAD];
__device__ int   g_scan[NPAD];
__device__ int   g_bsum[256];
__device__ int   g_off[NN + 1];
__device__ int   g_pos[NN];
__device__ int   g_es[EE];                // src, sorted by dst
__device__ int   g_eid[EE];               // original edge id, sorted by dst

// ---------------------------------------------------------------------------
__global__ void k_init() {
    int i = blockIdx.x * blockDim.x + threadIdx.x;
    int stride = gridDim.x * blockDim.x;
    for (int j = i; j < NPAD; j += stride) g_cnt[j] = 0;
    for (int j = i; j < NN; j += stride) g_pos[j] = 0;
}

// ---------------- counting sort by dst --------------------------------------
__global__ void k_hist(const int* __restrict__ ei) {
    int e = blockIdx.x * blockDim.x + threadIdx.x;
    if (e >= EE) return;
    atomicAdd(&g_cnt[ei[EE + e]], 1);
}

__global__ void k_scanA() {
    __shared__ int sh[256];
    int b = blockIdx.x, t = threadIdx.x;
    int i = b * 256 + t;
    int v = g_cnt[i];
    sh[t] = v;
    __syncthreads();
#pragma unroll
    for (int o = 1; o < 256; o <<= 1) {
        int x = (t >= o) ? sh[t - o] : 0;
        __syncthreads();
        sh[t] += x;
        __syncthreads();
    }
    g_scan[i] = sh[t];
    if (t == 255) g_bsum[b] = sh[255];
}

__global__ void k_scanB() {
    __shared__ int sh[256];
    int t = threadIdx.x;
    int v = (t < NBLK) ? g_bsum[t] : 0;
    sh[t] = v;
    __syncthreads();
#pragma unroll
    for (int o = 1; o < 256; o <<= 1) {
        int x = (t >= o) ? sh[t - o] : 0;
        __syncthreads();
        sh[t] += x;
        __syncthreads();
    }
    g_bsum[t] = sh[t] - v;   // exclusive
    if (t == 0) g_off[NN] = EE;
}

__global__ void k_scanC() {
    int i = blockIdx.x * blockDim.x + threadIdx.x;
    if (i >= NN) return;
    g_off[i] = g_scan[i] - g_cnt[i] + g_bsum[i >> 8];  // exclusive prefix
}

__global__ void k_scatter(const int* __restrict__ ei) {
    int e = blockIdx.x * blockDim.x + threadIdx.x;
    if (e >= EE) return;
    int s = ei[e];
    int d = ei[EE + e];
    int p = g_off[d] + atomicAdd(&g_pos[d], 1);
    g_es[p] = s;
    g_eid[p] = e;
}

// ---------------- fused q/k/v GEMM + epilogue -------------------------------
#define BM 128
#define BK 16
__global__ void __launch_bounds__(256, 2)
k_gemm(const float* __restrict__ x,
       const float* __restrict__ Wq, const float* __restrict__ bq,
       const float* __restrict__ Wk, const float* __restrict__ bk,
       const float* __restrict__ Wv, const float* __restrict__ bv) {
    int which = blockIdx.y >> 2;
    int h = blockIdx.y & 3;
    const float* W = (which == 0) ? Wq : ((which == 1) ? Wk : Wv);
    const float* b = (which == 0) ? bq : ((which == 1) ? bk : bv);
    W += h * DD * KDIM;
    b += h * DD;
    int n0 = blockIdx.x * BM;

    __shared__ float As[BK][BM + 4];
    __shared__ float Bs[BK][DD + 4];
    __shared__ float red[BM][17];
    __shared__ float fac[BM];

    int t = threadIdx.x;
    int tx = t & 15, ty = t >> 4;

    float acc[8][8];
#pragma unroll
    for (int j = 0; j < 8; j++)
#pragma unroll
        for (int c = 0; c < 8; c++) acc[j][c] = 0.f;

    for (int kk = 0; kk < KDIM; kk += BK) {
#pragma unroll
        for (int r = 0; r < 8; r++) {
            int idx = r * 256 + t;
            int m = idx >> 4, k = idx & 15;
            int gi = kk + k, gn = n0 + m;
            float v = 0.f;
            if (gi < KDIM && gn < NN) v = x[(size_t)gn * KDIM + gi];
            As[k][m] = v;
        }
#pragma unroll
        for (int r = 0; r < 8; r++) {
            int idx = r * 256 + t;
            int o = idx >> 4, k = idx & 15;
            int gi = kk + k;
            float v = 0.f;
            if (gi < KDIM) v = W[o * KDIM + gi];
            Bs[k][o] = v;
        }
        __syncthreads();
#pragma unroll
        for (int k = 0; k < BK; k++) {
            float4 a0 = *(const float4*)&As[k][ty * 8];
            float4 a1 = *(const float4*)&As[k][ty * 8 + 4];
            float4 b0 = *(const float4*)&Bs[k][tx * 8];
            float4 b1 = *(const float4*)&Bs[k][tx * 8 + 4];
            float a[8] = {a0.x, a0.y, a0.z, a0.w, a1.x, a1.y, a1.z, a1.w};
            float bb[8] = {b0.x, b0.y, b0.z, b0.w, b1.x, b1.y, b1.z, b1.w};
#pragma unroll
            for (int j = 0; j < 8; j++)
#pragma unroll
                for (int c = 0; c < 8; c++) acc[j][c] = fmaf(a[j], bb[c], acc[j][c]);
        }
        __syncthreads();
    }

#pragma unroll
    for (int c = 0; c < 8; c++) {
        float bb = b[tx * 8 + c];
#pragma unroll
        for (int j = 0; j < 8; j++) acc[j][c] += bb;
    }

#pragma unroll
    for (int j = 0; j < 8; j++) {
        float s = 0.f;
#pragma unroll
        for (int c = 0; c < 8; c++) s = fmaf(acc[j][c], acc[j][c], s);
        red[ty * 8 + j][tx] = s;
    }
    __syncthreads();
    if (t < BM) {
        float ss = 0.f;
#pragma unroll
        for (int i = 0; i < 16; i++) ss += red[t][i];
        int gn = n0 + t;
        if (which == 2) {
            float ns = sqrtf(ss);
            fac[t] = asinhf(ns) / fmaxf(ns, EPSF);
        } else {
            fac[t] = 1.f;
            if (gn < NN) {
                float* dst = (which == 0) ? g_q : g_k;
                dst[((size_t)gn * HH + h) * QKS + 128] = sqrtf(ss + 1.0f);
            }
        }
    }
    __syncthreads();

#pragma unroll
    for (int j = 0; j < 8; j++) {
        int m = ty * 8 + j;
        int gn = n0 + m;
        if (gn >= NN) continue;
        float f = fac[m];
        float4 v0 = make_float4(acc[j][0] * f, acc[j][1] * f, acc[j][2] * f, acc[j][3] * f);
        float4 v1 = make_float4(acc[j][4] * f, acc[j][5] * f, acc[j][6] * f, acc[j][7] * f);
        float* base;
        if (which == 2) base = g_tan + ((size_t)gn * HH + h) * DD;
        else            base = ((which == 0) ? g_q : g_k) + ((size_t)gn * HH + h) * QKS;
        ((float4*)(base + tx * 8))[0] = v0;
        ((float4*)(base + tx * 8))[1] = v1;
    }
}

// ---------------- edge phase ------------------------------------------------
// warp per sorted edge position: logits for all 4 heads (no atomics)
__global__ void k_edge1(const int* __restrict__ ei,
                        const float* __restrict__ ef,
                        const float* __restrict__ We) {
    int p = (blockIdx.x * blockDim.x + threadIdx.x) >> 5;
    int lane = threadIdx.x & 31;
    if (p >= EE) return;
    int s = g_es[p];
    int d = ei[EE + g_eid[p]];     // dst (sorted-adjacent, cached)
    float efl = __ldg(ef + (size_t)g_eid[p] * EDD + lane);

    const float* qb = g_q + (size_t)d * (HH * QKS);
    const float* kb = g_k + (size_t)s * (HH * QKS);
    float part[HH];
#pragma unroll
    for (int h = 0; h < HH; h++) {
        const float* qh = qb + h * QKS;
        const float* kh = kb + h * QKS;
        float4 q4 = __ldg((const float4*)qh + lane);
        float4 k4 = __ldg((const float4*)kh + lane);
        float pp = q4.x * k4.x + q4.y * k4.y + q4.z * k4.z + q4.w * k4.w;
        if (lane == 0) pp = fmaf(-__ldg(qh + 128), __ldg(kh + 128), pp);
        pp = fmaf(CHALF * efl, __ldg(We + h * EDD + lane), pp);
        part[h] = pp;
    }
#pragma unroll
    for (int off = 16; off > 0; off >>= 1) {
#pragma unroll
        for (int h = 0; h < HH; h++)
            part[h] += __shfl_xor_sync(0xffffffffu, part[h], off);
    }
    if (lane < HH)
        g_logits[(size_t)p * HH + lane] = (2.f + 2.f * part[lane]) * SCALE_INV;
}

// warp per dst node: segmented softmax + weighted tan aggregation + expmap out
__global__ void k_edge3(float* __restrict__ out) {
    int d = (blockIdx.x * blockDim.x + threadIdx.x) >> 5;
    int lane = threadIdx.x & 31;
    if (d >= NN) return;
    int s0 = g_off[d], s1 = g_off[d + 1];
    const float4* lg4 = (const float4*)g_logits;

    // pass 1: per-head max
    float4 mx = make_float4(-1e30f, -1e30f, -1e30f, -1e30f);
    for (int p = s0 + lane; p < s1; p += 32) {
        float4 l = __ldg(lg4 + p);
        mx.x = fmaxf(mx.x, l.x); mx.y = fmaxf(mx.y, l.y);
        mx.z = fmaxf(mx.z, l.z); mx.w = fmaxf(mx.w, l.w);
    }
#pragma unroll
    for (int off = 16; off > 0; off >>= 1) {
        mx.x = fmaxf(mx.x, __shfl_xor_sync(0xffffffffu, mx.x, off));
        mx.y = fmaxf(mx.y, __shfl_xor_sync(0xffffffffu, mx.y, off));
        mx.z = fmaxf(mx.z, __shfl_xor_sync(0xffffffffu, mx.z, off));
        mx.w = fmaxf(mx.w, __shfl_xor_sync(0xffffffffu, mx.w, off));
    }

    // pass 2: per-head denominator
    float4 sm = make_float4(0.f, 0.f, 0.f, 0.f);
    for (int p = s0 + lane; p < s1; p += 32) {
        float4 l = __ldg(lg4 + p);
        sm.x += __expf(l.x - mx.x); sm.y += __expf(l.y - mx.y);
        sm.z += __expf(l.z - mx.z); sm.w += __expf(l.w - mx.w);
    }
#pragma unroll
    for (int off = 16; off > 0; off >>= 1) {
        sm.x += __shfl_xor_sync(0xffffffffu, sm.x, off);
        sm.y += __shfl_xor_sync(0xffffffffu, sm.y, off);
        sm.z += __shfl_xor_sync(0xffffffffu, sm.z, off);
        sm.w += __shfl_xor_sync(0xffffffffu, sm.w, off);
    }
    float4 rd;
    rd.x = (sm.x > 0.f) ? 1.f / sm.x : 0.f;
    rd.y = (sm.y > 0.f) ? 1.f / sm.y : 0.f;
    rd.z = (sm.z > 0.f) ? 1.f / sm.z : 0.f;
    rd.w = (sm.w > 0.f) ? 1.f / sm.w : 0.f;

    // pass 3: accumulate alpha * tan[src]; lane owns dims [4*lane, 4*lane+4)
    float4 a0 = make_float4(0, 0, 0, 0), a1 = a0, a2 = a0, a3 = a0;
    for (int p = s0; p < s1; p++) {
        float4 l = __ldg(lg4 + p);                 // uniform
        float w0 = __expf(l.x - mx.x) * rd.x;
        float w1 = __expf(l.y - mx.y) * rd.y;
        float w2 = __expf(l.z - mx.z) * rd.z;
        float w3 = __expf(l.w - mx.w) * rd.w;
        int s = g_es[p];                            // uniform
        const float4* tb = (const float4*)(g_tan + (size_t)s * (HH * DD));
        float4 t0 = __ldg(tb + lane);
        float4 t1 = __ldg(tb + 32 + lane);
        float4 t2 = __ldg(tb + 64 + lane);
        float4 t3 = __ldg(tb + 96 + lane);
        a0.x = fmaf(w0, t0.x, a0.x); a0.y = fmaf(w0, t0.y, a0.y);
        a0.z = fmaf(w0, t0.z, a0.z); a0.w = fmaf(w0, t0.w, a0.w);
        a1.x = fmaf(w1, t1.x, a1.x); a1.y = fmaf(w1, t1.y, a1.y);
        a1.z = fmaf(w1, t1.z, a1.z); a1.w = fmaf(w1, t1.w, a1.w);
        a2.x = fmaf(w2, t2.x, a2.x); a2.y = fmaf(w2, t2.y, a2.y);
        a2.z = fmaf(w2, t2.z, a2.z); a2.w = fmaf(w2, t2.w, a2.w);
        a3.x = fmaf(w3, t3.x, a3.x); a3.y = fmaf(w3, t3.y, a3.y);
        a3.z = fmaf(w3, t3.z, a3.z); a3.w = fmaf(w3, t3.w, a3.w);
    }

    // mean over heads
    float4 ms;
    ms.x = (a0.x + a1.x + a2.x + a3.x) * 0.25f;
    ms.y = (a0.y + a1.y + a2.y + a3.y) * 0.25f;
    ms.z = (a0.z + a1.z + a2.z + a3.z) * 0.25f;
    ms.w = (a0.w + a1.w + a2.w + a3.w) * 0.25f;

    // expmap0
    float ss = ms.x * ms.x + ms.y * ms.y + ms.z * ms.z + ms.w * ms.w;
#pragma unroll
    for (int off = 16; off > 0; off >>= 1) ss += __shfl_xor_sync(0xffffffffu, ss, off);
    float nrm = sqrtf(ss);
    float f = sinhf(nrm) / fmaxf(nrm, EPSF);
    float* op = out + (size_t)d * KDIM;
    if (lane == 0) op[0] = coshf(nrm);
    float* sp = op + 1 + lane * 4;
    sp[0] = f * ms.x; sp[1] = f * ms.y; sp[2] = f * ms.z; sp[3] = f * ms.w;
}

// ---------------------------------------------------------------------------
extern "C" void kernel_launch(void* const* d_in, const int* in_sizes, int n_in,
                              void* d_out, int out_size) {
    const float* x  = (const float*)d_in[0];
    const int*   ei = (const int*)d_in[1];
    const float* ef = (const float*)d_in[2];
    const float* Wq = (const float*)d_in[3];
    const float* bq = (const float*)d_in[4];
    const float* Wk = (const float*)d_in[5];
    const float* bk = (const float*)d_in[6];
    const float* Wv = (const float*)d_in[7];
    const float* bv = (const float*)d_in[8];
    const float* We = (const float*)d_in[9];
    float* out = (float*)d_out;

    k_init<<<256, 256>>>();
    k_hist<<<(EE + 255) / 256, 256>>>(ei);
    k_scanA<<<NBLK, 256>>>();
    k_scanB<<<1, 256>>>();
    k_scanC<<<(NN + 255) / 256, 256>>>();
    k_scatter<<<(EE + 255) / 256, 256>>>(ei);
    k_gemm<<<dim3((NN + BM - 1) / BM, 12), 256>>>(x, Wq, bq, Wk, bk, Wv, bv);
    k_edge1<<<(EE * 32) / 256, 256>>>(ei, ef, We);
    k_edge3<<<(NN * 32 + 255) / 256, 256>>>(out);
}

// round 5
// speedup vs baseline: 1.3800x; 1.3800x over previous
#include <cuda_runtime.h>
#include <math.h>

// Problem constants
#define NN   50000
#define EE   800000
#define DD   128
#define HH   4
#define EDD  32
#define KDIM 129          // D+1 input dim
#define QKS  132          // per-(n,h) stride for q/k: [space 0..127, time at 128, pad]
#define EPSF 1e-8f
#define SCALE_INV 0.08838834764831845f   // 1/sqrt(128)
#define CHALF     5.656854249492381f     // sqrt(128)/2

#define NPAD 50176        // NN padded to 256 multiple (196 blocks)
#define NBLK 196

// ---------------- scratch (static device globals; no allocation) -------------
__device__ float g_q[NN * HH * QKS];      // 105.6 MB
__device__ float g_k[NN * HH * QKS];      // 105.6 MB
__device__ float g_tan[NN * HH * DD];     // 102.4 MB
__device__ float g_logits[EE * HH];       // 12.8 MB (then exp values)
__device__ float g_m[NN * HH];
__device__ float g_den[NN * HH];
__device__ float g_agg[NN * DD];          // 25.6 MB (head-fused accumulator)
__device__ int   g_cnt[NPAD];
__device__ int   g_scan[NPAD];
__device__ int   g_bsum[256];
__device__ int   g_off[NN + 1];
__device__ int   g_pos[NN];
__device__ int   g_es[EE];                // src, sorted by src
__device__ int   g_ed[EE];                // dst, sorted by src
__device__ int   g_eid[EE];               // original edge id, sorted by src

// ---------------------------------------------------------------------------
__global__ void k_init() {
    int i = blockIdx.x * blockDim.x + threadIdx.x;
    int stride = gridDim.x * blockDim.x;
    for (int j = i; j < NN * DD; j += stride) g_agg[j] = 0.f;
    for (int j = i; j < NN * HH; j += stride) { g_m[j] = -3.0e38f; g_den[j] = 0.f; }
    for (int j = i; j < NPAD; j += stride) g_cnt[j] = 0;
    for (int j = i; j < NN; j += stride) g_pos[j] = 0;
}

// ---------------- counting sort by SRC --------------------------------------
__global__ void k_hist(const int* __restrict__ ei) {
    int e = blockIdx.x * blockDim.x + threadIdx.x;
    if (e >= EE) return;
    atomicAdd(&g_cnt[ei[e]], 1);
}

__global__ void k_scanA() {
    __shared__ int sh[256];
    int b = blockIdx.x, t = threadIdx.x;
    int i = b * 256 + t;
    int v = g_cnt[i];
    sh[t] = v;
    __syncthreads();
#pragma unroll
    for (int o = 1; o < 256; o <<= 1) {
        int x = (t >= o) ? sh[t - o] : 0;
        __syncthreads();
        sh[t] += x;
        __syncthreads();
    }
    g_scan[i] = sh[t];
    if (t == 255) g_bsum[b] = sh[255];
}

__global__ void k_scanB() {
    __shared__ int sh[256];
    int t = threadIdx.x;
    int v = (t < NBLK) ? g_bsum[t] : 0;
    sh[t] = v;
    __syncthreads();
#pragma unroll
    for (int o = 1; o < 256; o <<= 1) {
        int x = (t >= o) ? sh[t - o] : 0;
        __syncthreads();
        sh[t] += x;
        __syncthreads();
    }
    g_bsum[t] = sh[t] - v;   // exclusive
    if (t == 0) g_off[NN] = EE;
}

__global__ void k_scanC() {
    int i = blockIdx.x * blockDim.x + threadIdx.x;
    if (i >= NN) return;
    g_off[i] = g_scan[i] - g_cnt[i] + g_bsum[i >> 8];  // exclusive prefix
}

__global__ void k_scatter(const int* __restrict__ ei) {
    int e = blockIdx.x * blockDim.x + threadIdx.x;
    if (e >= EE) return;
    int s = ei[e];
    int d = ei[EE + e];
    int p = g_off[s] + atomicAdd(&g_pos[s], 1);
    g_es[p] = s;
    g_ed[p] = d;
    g_eid[p] = e;
}

// ---------------- fused q/k/v GEMM + epilogue -------------------------------
#define BM 128
#define BK 16
__global__ void __launch_bounds__(256, 2)
k_gemm(const float* __restrict__ x,
       const float* __restrict__ Wq, const float* __restrict__ bq,
       const float* __restrict__ Wk, const float* __restrict__ bk,
       const float* __restrict__ Wv, const float* __restrict__ bv) {
    int which = blockIdx.y >> 2;
    int h = blockIdx.y & 3;
    const float* W = (which == 0) ? Wq : ((which == 1) ? Wk : Wv);
    const float* b = (which == 0) ? bq : ((which == 1) ? bk : bv);
    W += h * DD * KDIM;
    b += h * DD;
    int n0 = blockIdx.x * BM;

    __shared__ float As[BK][BM + 4];
    __shared__ float Bs[BK][DD + 4];
    __shared__ float red[BM][17];
    __shared__ float fac[BM];

    int t = threadIdx.x;
    int tx = t & 15, ty = t >> 4;

    float acc[8][8];
#pragma unroll
    for (int j = 0; j < 8; j++)
#pragma unroll
        for (int c = 0; c < 8; c++) acc[j][c] = 0.f;

    for (int kk = 0; kk < KDIM; kk += BK) {
#pragma unroll
        for (int r = 0; r < 8; r++) {
            int idx = r * 256 + t;
            int m = idx >> 4, k = idx & 15;
            int gi = kk + k, gn = n0 + m;
            float v = 0.f;
            if (gi < KDIM && gn < NN) v = x[(size_t)gn * KDIM + gi];
            As[k][m] = v;
        }
#pragma unroll
        for (int r = 0; r < 8; r++) {
            int idx = r * 256 + t;
            int o = idx >> 4, k = idx & 15;
            int gi = kk + k;
            float v = 0.f;
            if (gi < KDIM) v = W[o * KDIM + gi];
            Bs[k][o] = v;
        }
        __syncthreads();
#pragma unroll
        for (int k = 0; k < BK; k++) {
            float4 a0 = *(const float4*)&As[k][ty * 8];
            float4 a1 = *(const float4*)&As[k][ty * 8 + 4];
            float4 b0 = *(const float4*)&Bs[k][tx * 8];
            float4 b1 = *(const float4*)&Bs[k][tx * 8 + 4];
            float a[8] = {a0.x, a0.y, a0.z, a0.w, a1.x, a1.y, a1.z, a1.w};
            float bb[8] = {b0.x, b0.y, b0.z, b0.w, b1.x, b1.y, b1.z, b1.w};
#pragma unroll
            for (int j = 0; j < 8; j++)
#pragma unroll
                for (int c = 0; c < 8; c++) acc[j][c] = fmaf(a[j], bb[c], acc[j][c]);
        }
        __syncthreads();
    }

#pragma unroll
    for (int c = 0; c < 8; c++) {
        float bb = b[tx * 8 + c];
#pragma unroll
        for (int j = 0; j < 8; j++) acc[j][c] += bb;
    }

#pragma unroll
    for (int j = 0; j < 8; j++) {
        float s = 0.f;
#pragma unroll
        for (int c = 0; c < 8; c++) s = fmaf(acc[j][c], acc[j][c], s);
        red[ty * 8 + j][tx] = s;
    }
    __syncthreads();
    if (t < BM) {
        float ss = 0.f;
#pragma unroll
        for (int i = 0; i < 16; i++) ss += red[t][i];
        int gn = n0 + t;
        if (which == 2) {
            float ns = sqrtf(ss);
            fac[t] = asinhf(ns) / fmaxf(ns, EPSF);
        } else {
            fac[t] = 1.f;
            if (gn < NN) {
                float* dst = (which == 0) ? g_q : g_k;
                dst[((size_t)gn * HH + h) * QKS + 128] = sqrtf(ss + 1.0f);
            }
        }
    }
    __syncthreads();

#pragma unroll
    for (int j = 0; j < 8; j++) {
        int m = ty * 8 + j;
        int gn = n0 + m;
        if (gn >= NN) continue;
        float f = fac[m];
        float4 v0 = make_float4(acc[j][0] * f, acc[j][1] * f, acc[j][2] * f, acc[j][3] * f);
        float4 v1 = make_float4(acc[j][4] * f, acc[j][5] * f, acc[j][6] * f, acc[j][7] * f);
        float* base;
        if (which == 2) base = g_tan + ((size_t)gn * HH + h) * DD;
        else            base = ((which == 0) ? g_q : g_k) + ((size_t)gn * HH + h) * QKS;
        ((float4*)(base + tx * 8))[0] = v0;
        ((float4*)(base + tx * 8))[1] = v1;
    }
}

// ---------------- edge phase (edges sorted by src) ---------------------------
__device__ __forceinline__ void atomicMaxF(float* addr, float v) {
    if (v >= 0.f) atomicMax((int*)addr, __float_as_int(v));
    else          atomicMin((unsigned int*)addr, __float_as_uint(v));
}

// warp per sorted edge: logits for 4 heads; k[src] L1/L2-cached via sort.
__global__ void k_edge1(const float* __restrict__ ef,
                        const float* __restrict__ We) {
    int p = (blockIdx.x * blockDim.x + threadIdx.x) >> 5;
    int lane = threadIdx.x & 31;
    if (p >= EE) return;
    int s = g_es[p];
    int d = g_ed[p];
    int e = g_eid[p];
    float efl = __ldg(ef + (size_t)e * EDD + lane);

    const float* qb = g_q + (size_t)d * (HH * QKS);
    const float* kb = g_k + (size_t)s * (HH * QKS);
    float part[HH];
#pragma unroll
    for (int h = 0; h < HH; h++) {
        const float* qh = qb + h * QKS;
        const float* kh = kb + h * QKS;
        float4 q4 = __ldg((const float4*)qh + lane);
        float4 k4 = __ldg((const float4*)kh + lane);
        float pp = q4.x * k4.x + q4.y * k4.y + q4.z * k4.z + q4.w * k4.w;
        if (lane == 0) pp = fmaf(-__ldg(qh + 128), __ldg(kh + 128), pp);
        pp = fmaf(CHALF * efl, __ldg(We + h * EDD + lane), pp);
        part[h] = pp;
    }
#pragma unroll
    for (int off = 16; off > 0; off >>= 1) {
#pragma unroll
        for (int h = 0; h < HH; h++)
            part[h] += __shfl_xor_sync(0xffffffffu, part[h], off);
    }
    if (lane < HH) {
        float logit = (2.f + 2.f * part[lane]) * SCALE_INV;
        g_logits[(size_t)p * HH + lane] = logit;
        atomicMaxF(&g_m[(size_t)d * HH + lane], logit);
    }
}

// thread per (sorted-edge, head): exp + denominator
__global__ void k_edge2() {
    int idx = blockIdx.x * blockDim.x + threadIdx.x;
    if (idx >= EE * HH) return;
    int p = idx >> 2, h = idx & 3;
    int d = g_ed[p];
    float ex = __expf(g_logits[idx] - g_m[(size_t)d * HH + h]);
    g_logits[idx] = ex;
    atomicAdd(&g_den[(size_t)d * HH + h], ex);
}

// warp per sorted edge: head-fused alpha*tan scatter via red.v4.
// tan[src] is cached (src-sorted); red target is the 25.6MB g_agg (L2-resident).
__global__ void k_edge3() {
    int p = (blockIdx.x * blockDim.x + threadIdx.x) >> 5;
    int lane = threadIdx.x & 31;
    if (p >= EE) return;
    int s = g_es[p];
    int d = g_ed[p];
    float a_l = 0.f;
    if (lane < HH) a_l = g_logits[(size_t)p * HH + lane] /
                         g_den[(size_t)d * HH + lane];
    float alpha[HH];
#pragma unroll
    for (int h = 0; h < HH; h++) alpha[h] = __shfl_sync(0xffffffffu, a_l, h);

    const float4* tb = (const float4*)(g_tan + (size_t)s * (HH * DD));
    float4 t0 = __ldg(tb + lane);
    float4 t1 = __ldg(tb + 32 + lane);
    float4 t2 = __ldg(tb + 64 + lane);
    float4 t3 = __ldg(tb + 96 + lane);
    float cx = alpha[0] * t0.x + alpha[1] * t1.x + alpha[2] * t2.x + alpha[3] * t3.x;
    float cy = alpha[0] * t0.y + alpha[1] * t1.y + alpha[2] * t2.y + alpha[3] * t3.y;
    float cz = alpha[0] * t0.z + alpha[1] * t1.z + alpha[2] * t2.z + alpha[3] * t3.z;
    float cw = alpha[0] * t0.w + alpha[1] * t1.w + alpha[2] * t2.w + alpha[3] * t3.w;
    float* dp = g_agg + (size_t)d * DD + lane * 4;
    asm volatile("red.global.add.v4.f32 [%0], {%1, %2, %3, %4};"
                 :: "l"(dp), "f"(cx), "f"(cy), "f"(cz), "f"(cw) : "memory");
}

// ---------------- output: mean over heads + expmap0 -------------------------
__global__ void k_out(float* __restrict__ out) {
    int w = (blockIdx.x * blockDim.x + threadIdx.x) >> 5;
    int lane = threadIdx.x & 31;
    if (w >= NN) return;
    float4 v = ((const float4*)g_agg)[(size_t)w * 32 + lane];
    float4 ms = make_float4(v.x * 0.25f, v.y * 0.25f, v.z * 0.25f, v.w * 0.25f);
    float ss = ms.x * ms.x + ms.y * ms.y + ms.z * ms.z + ms.w * ms.w;
#pragma unroll
    for (int off = 16; off > 0; off >>= 1) ss += __shfl_xor_sync(0xffffffffu, ss, off);
    float nrm = sqrtf(ss);
    float f = sinhf(nrm) / fmaxf(nrm, EPSF);
    float* op = out + (size_t)w * KDIM;
    if (lane == 0) op[0] = coshf(nrm);
    float* sp = op + 1 + lane * 4;
    sp[0] = f * ms.x; sp[1] = f * ms.y; sp[2] = f * ms.z; sp[3] = f * ms.w;
}

// ---------------------------------------------------------------------------
extern "C" void kernel_launch(void* const* d_in, const int* in_sizes, int n_in,
                              void* d_out, int out_size) {
    const float* x  = (const float*)d_in[0];
    const int*   ei = (const int*)d_in[1];
    const float* ef = (const float*)d_in[2];
    const float* Wq = (const float*)d_in[3];
    const float* bq = (const float*)d_in[4];
    const float* Wk = (const float*)d_in[5];
    const float* bk = (const float*)d_in[6];
    const float* Wv = (const float*)d_in[7];
    const float* bv = (const float*)d_in[8];
    const float* We = (const float*)d_in[9];
    float* out = (float*)d_out;

    k_init<<<2048, 256>>>();
    k_hist<<<(EE + 255) / 256, 256>>>(ei);
    k_scanA<<<NBLK, 256>>>();
    k_scanB<<<1, 256>>>();
    k_scanC<<<(NN + 255) / 256, 256>>>();
    k_scatter<<<(EE + 255) / 256, 256>>>(ei);
    k_gemm<<<dim3((NN + BM - 1) / BM, 12), 256>>>(x, Wq, bq, Wk, bk, Wv, bv);
    k_edge1<<<(EE * 32) / 256, 256>>>(ef, We);
    k_edge2<<<(EE * HH + 255) / 256, 256>>>();
    k_edge3<<<(EE * 32) / 256, 256>>>();
    k_out<<<(NN * 32 + 255) / 256, 256>>>(out);
}